// round 1
// baseline (speedup 1.0000x reference)
#include <cuda_runtime.h>

#define NB 1024
#define NL 4096
#define NT 256
#define PER 16            // NL / NT
#define NWARP (NT / 32)
#define TAUF 0.85f

__device__ float g_row[NB];

__global__ __launch_bounds__(NT)
void row_kernel(const float* __restrict__ probs, const int* __restrict__ labels) {
    const int row = blockIdx.x;
    const int t = threadIdx.x;
    const int lane = t & 31;
    const int warp = t >> 5;

    const int4*   lab4 = reinterpret_cast<const int4*>(labels + (size_t)row * NL) + t * (PER / 4);
    const float4* p4   = reinterpret_cast<const float4*>(probs + (size_t)row * NL) + t * (PER / 4);

    // Front-batched loads: 8 wide loads in flight per thread (hides DRAM latency).
    int4   lv[4];
    float4 pv[4];
#pragma unroll
    for (int i = 0; i < 4; i++) lv[i] = lab4[i];
#pragma unroll
    for (int i = 0; i < 4; i++) pv[i] = p4[i];

    int v[PER];
    float p[PER];
#pragma unroll
    for (int i = 0; i < 4; i++) {
        v[4*i+0] = lv[i].x; v[4*i+1] = lv[i].y; v[4*i+2] = lv[i].z; v[4*i+3] = lv[i].w;
        p[4*i+0] = pv[i].x; p[4*i+1] = pv[i].y; p[4*i+2] = pv[i].z; p[4*i+3] = pv[i].w;
    }

    int s = 0;
#pragma unroll
    for (int i = 0; i < PER; i++) s += v[i];

    // Warp-inclusive scan of per-thread chunk sums.
    int inc = s;
#pragma unroll
    for (int d = 1; d < 32; d <<= 1) {
        int n = __shfl_up_sync(0xffffffffu, inc, d);
        if (lane >= d) inc += n;
    }

    __shared__ int wsum[NWARP];
    __shared__ int woff[NWARP + 1];
    if (lane == 31) wsum[warp] = inc;
    __syncthreads();
    if (t == 0) {
        int acc = 0;
#pragma unroll
        for (int w = 0; w < NWARP; w++) { woff[w] = acc; acc += wsum[w]; }
        woff[NWARP] = acc;
    }
    __syncthreads();

    const int T   = woff[NWARP];            // row total of labels
    int c         = woff[warp] + (inc - s); // exclusive prefix for this thread's chunk
    const float invTau = 1.0f / TAUF;
    const float twoInvTau = 2.0f * invTau;

    // k+T for the first element of this chunk (k = global_idx + 1)
    const int kbase = t * PER + 1 + T;

    float S = 0.0f, W = 0.0f;
#pragma unroll
    for (int j = 0; j < PER; j++) {
        c += v[j];
        float a = 0.0f;                     // a = r / tau
        if (c > 0)
            a = __fdividef(twoInvTau * (float)c, (float)(kbase + j));
        float e = __expf(a);
        S += e;
        W += e * (a - __logf(p[j]));
    }

    // Block reduce (S, W)
#pragma unroll
    for (int d = 16; d; d >>= 1) {
        S += __shfl_down_sync(0xffffffffu, S, d);
        W += __shfl_down_sync(0xffffffffu, W, d);
    }
    __shared__ float sS[NWARP], sW[NWARP];
    if (lane == 0) { sS[warp] = S; sW[warp] = W; }
    __syncthreads();
    if (t == 0) {
        float St = 0.0f, Wt = 0.0f;
#pragma unroll
        for (int w = 0; w < NWARP; w++) { St += sS[w]; Wt += sW[w]; }
        // row contribution: W/S - log(S)   (sum_i q_i (log q_i - log p_i))
        g_row[row] = Wt / St - __logf(St);
    }
}

__global__ __launch_bounds__(NT)
void reduce_kernel(float* __restrict__ d_out) {
    const int t = threadIdx.x;
    float s = 0.0f;
    for (int i = t; i < NB; i += NT) s += g_row[i];
#pragma unroll
    for (int d = 16; d; d >>= 1) s += __shfl_down_sync(0xffffffffu, s, d);
    __shared__ float sm[NWARP];
    if ((t & 31) == 0) sm[t >> 5] = s;
    __syncthreads();
    if (t == 0) {
        float tot = 0.0f;
#pragma unroll
        for (int w = 0; w < NWARP; w++) tot += sm[w];
        d_out[0] = tot * (1.0f / (float)NB);
    }
}

extern "C" void kernel_launch(void* const* d_in, const int* in_sizes, int n_in,
                              void* d_out, int out_size) {
    const float* probs  = (const float*)d_in[0];   // output: (B, L, 1) f32
    const int*   labels = (const int*)d_in[1];     // labels: (B, L) i32
    float* out = (float*)d_out;

    row_kernel<<<NB, NT>>>(probs, labels);
    reduce_kernel<<<1, NT>>>(out);
}

// round 3
// speedup vs baseline: 1.1805x; 1.1805x over previous
#include <cuda_runtime.h>

#define NB 1024
#define NL 4096
#define NT 512
#define PER 8             // NL / NT
#define NWARP (NT / 32)   // 16
#define TAUF 0.85f

__device__ float g_row[NB];
__device__ unsigned g_count = 0;   // self-resetting via atomicInc wraparound

__global__ __launch_bounds__(NT)
void fused_kernel(const float* __restrict__ probs, const int* __restrict__ labels,
                  float* __restrict__ d_out) {
    const int row  = blockIdx.x;
    const int t    = threadIdx.x;
    const int lane = t & 31;
    const int warp = t >> 5;

    const int4*   lab4 = reinterpret_cast<const int4*>(labels + (size_t)row * NL) + t * (PER / 4);
    const float4* p4   = reinterpret_cast<const float4*>(probs  + (size_t)row * NL) + t * (PER / 4);

    // Front-batched wide loads (4 × LDG.128 per thread in flight).
    int4   lv[2];
    float4 pv[2];
#pragma unroll
    for (int i = 0; i < 2; i++) lv[i] = lab4[i];
#pragma unroll
    for (int i = 0; i < 2; i++) pv[i] = p4[i];

    int   v[PER];
    float p[PER];
#pragma unroll
    for (int i = 0; i < 2; i++) {
        v[4*i+0] = lv[i].x; v[4*i+1] = lv[i].y; v[4*i+2] = lv[i].z; v[4*i+3] = lv[i].w;
        p[4*i+0] = pv[i].x; p[4*i+1] = pv[i].y; p[4*i+2] = pv[i].z; p[4*i+3] = pv[i].w;
    }

    int s = 0;
#pragma unroll
    for (int i = 0; i < PER; i++) s += v[i];

    // Warp-inclusive scan of per-thread chunk sums.
    int inc = s;
#pragma unroll
    for (int d = 1; d < 32; d <<= 1) {
        int n = __shfl_up_sync(0xffffffffu, inc, d);
        if (lane >= d) inc += n;
    }

    __shared__ int wsum[NWARP];
    __shared__ int woff[NWARP + 1];
    if (lane == 31) wsum[warp] = inc;
    __syncthreads();
    if (t == 0) {
        int acc = 0;
#pragma unroll
        for (int w = 0; w < NWARP; w++) { woff[w] = acc; acc += wsum[w]; }
        woff[NWARP] = acc;
    }
    __syncthreads();

    const int T = woff[NWARP];              // row total of labels
    int c       = woff[warp] + (inc - s);   // exclusive prefix for this thread's chunk
    const float twoInvTau = 2.0f / TAUF;
    const int kbase = t * PER + 1 + T;      // (k + T) at first element of chunk

    float S = 0.0f, W = 0.0f;
#pragma unroll
    for (int j = 0; j < PER; j++) {
        c += v[j];
        float a = 0.0f;                     // a = r / tau ; r = 2c/(k+T) when c>0
        if (c > 0)
            a = __fdividef(twoInvTau * (float)c, (float)(kbase + j));
        float e = __expf(a);
        S += e;
        W += e * (a - __logf(p[j]));
    }

    // Block reduce (S, W)
#pragma unroll
    for (int d = 16; d; d >>= 1) {
        S += __shfl_down_sync(0xffffffffu, S, d);
        W += __shfl_down_sync(0xffffffffu, W, d);
    }
    __shared__ float sS[NWARP], sW[NWARP];
    __shared__ int   s_last;
    if (lane == 0) { sS[warp] = S; sW[warp] = W; }
    __syncthreads();
    if (t == 0) {
        float St = 0.0f, Wt = 0.0f;
#pragma unroll
        for (int w = 0; w < NWARP; w++) { St += sS[w]; Wt += sW[w]; }
        g_row[row] = Wt / St - __logf(St);  // sum_i q_i (log q_i - log p_i)
        __threadfence();
        unsigned ticket = atomicInc(&g_count, NB - 1);   // wraps to 0 after NB calls
        s_last = (ticket == NB - 1);
    }
    __syncthreads();

    // Last-arriving CTA reduces all row values in a fixed (deterministic) order.
    if (s_last) {
        __threadfence();
        const volatile float* gr = g_row;
        float acc = 0.0f;
#pragma unroll
        for (int i = 0; i < NB / NT; i++) acc += gr[t + i * NT];
#pragma unroll
        for (int d = 16; d; d >>= 1) acc += __shfl_down_sync(0xffffffffu, acc, d);
        __shared__ float sm[NWARP];
        if (lane == 0) sm[warp] = acc;
        __syncthreads();
        if (t == 0) {
            float tot = 0.0f;
#pragma unroll
            for (int w = 0; w < NWARP; w++) tot += sm[w];
            d_out[0] = tot * (1.0f / (float)NB);
        }
    }
}

extern "C" void kernel_launch(void* const* d_in, const int* in_sizes, int n_in,
                              void* d_out, int out_size) {
    const float* probs  = (const float*)d_in[0];   // output: (B, L, 1) f32
    const int*   labels = (const int*)d_in[1];     // labels: (B, L) i32
    fused_kernel<<<NB, NT>>>(probs, labels, (float*)d_out);
}